// round 3
// baseline (speedup 1.0000x reference)
#include <cuda_runtime.h>
#include <math.h>
#include <float.h>

#define BB 64
#define CC 100
#define KK 5
#define NN (BB*CC*KK)      // 32000
#define NBINS 4096
#define NBLK 128           // >= ceil(NN/NTHR)=125, well under SM count for safe co-residency
#define NTHR 256
#define DMINF (-32.0f)
#define INVWF 64.0f        // NBINS / (32-(-32))

// ---------------- device scratch (no allocs allowed) ----------------
__device__ float g_t[NN], g_s[NN], g_d[NN];
__device__ float g_tk[KK*BB*CC], g_sk[KK*BB*CC];   // [k][b][c]
__device__ float g_ds[NN], g_tso[NN], g_sso[NN];   // bin-sorted
__device__ int   g_count[NBINS], g_cur[NBINS];
__device__ float g_binT[NBINS], g_binS[NBINS];
__device__ int   g_off[NBINS+1];
__device__ float g_PT[NBINS+1], g_PS[NBINS+1];
__device__ double g_tt, g_ss, g_ts, g_kl[KK], g_ce, g_l1, g_sub;
__device__ volatile unsigned g_barGen;
__device__ unsigned g_barCnt;

__device__ __forceinline__ int binOf(float x){
    int j = (int)floorf((x - DMINF) * INVWF);
    return min(max(j, 0), NBINS-1);
}

__device__ __forceinline__ void gridBar(){
    __syncthreads();
    if (threadIdx.x == 0){
        unsigned gen = g_barGen;
        __threadfence();
        if (atomicAdd(&g_barCnt, 1u) == NBLK-1u){
            g_barCnt = 0u;
            __threadfence();
            g_barGen = gen + 1u;
        } else {
            while (g_barGen == gen) { __nanosleep(64); }
            __threadfence();
        }
    }
    __syncthreads();
}

// block reduce (all 256 threads must call)
__device__ __forceinline__ float blockSum(float v, float* shR){
    int lane = threadIdx.x & 31, w = threadIdx.x >> 5;
    #pragma unroll
    for (int o=16;o;o>>=1) v += __shfl_down_sync(0xffffffffu, v, o);
    if (lane==0) shR[w] = v;
    __syncthreads();
    float r = 0.f;
    if (threadIdx.x==0){
        #pragma unroll
        for (int i=0;i<NTHR/32;i++) r += shR[i];
    }
    __syncthreads();
    return r;   // valid on tid 0 only
}

__global__ void __launch_bounds__(NTHR)
fused_kernel(const float* __restrict__ ls, const float* __restrict__ lt,
             const int* __restrict__ tgt, float* __restrict__ out)
{
    __shared__ int   shC[NTHR];
    __shared__ float shA[NTHR], shB[NTHR];
    __shared__ float shR[NTHR/32];

    const int tid  = threadIdx.x;
    const int bid  = blockIdx.x;
    const int lane = tid & 31;
    const int wid  = tid >> 5;

    // ================= Phase A: softmax + KD pieces + L2 dots + histogram =================
    {
        // BB*KK = 320 warp-tasks over 128 blocks * 8 warps = 1024 warps
        int gw = bid*(NTHR/32) + wid;          // global warp id
        if (gw < BB*KK){
            int b = gw / KK, k = gw % KK;
            float invT = 1.0f / (float)(k+1);
            float av[4], bv[4];
            float amax = -FLT_MAX, bmax = -FLT_MAX;
            #pragma unroll
            for (int q=0;q<4;q++){
                int c = lane + 32*q;
                bool ok = c < CC;
                av[q] = ok ? ls[b*CC+c]*invT : -FLT_MAX;
                bv[q] = ok ? lt[b*CC+c]*invT : -FLT_MAX;
                amax = fmaxf(amax, av[q]);
                bmax = fmaxf(bmax, bv[q]);
            }
            #pragma unroll
            for (int o=16;o;o>>=1){
                amax = fmaxf(amax, __shfl_xor_sync(0xffffffffu, amax, o));
                bmax = fmaxf(bmax, __shfl_xor_sync(0xffffffffu, bmax, o));
            }
            float ea[4], eb[4], sumA = 0.f, sumB = 0.f;
            #pragma unroll
            for (int q=0;q<4;q++){
                int c = lane + 32*q;
                ea[q] = (c<CC) ? expf(av[q]-amax) : 0.f;
                eb[q] = (c<CC) ? expf(bv[q]-bmax) : 0.f;
                sumA += ea[q]; sumB += eb[q];
            }
            #pragma unroll
            for (int o=16;o;o>>=1){
                sumA += __shfl_xor_sync(0xffffffffu, sumA, o);
                sumB += __shfl_xor_sync(0xffffffffu, sumB, o);
            }
            float lA = logf(sumA), lB = logf(sumB);
            float rA = 1.f/sumA, rB = 1.f/sumB;
            int tg = (k==0) ? tgt[b] : -1;
            float kl=0.f, tt=0.f, ssv=0.f, tsv=0.f;
            #pragma unroll
            for (int q=0;q<4;q++){
                int c = lane + 32*q;
                if (c < CC){
                    float lq = av[q]-amax-lA;      // log softmax student
                    float lp = bv[q]-bmax-lB;      // log softmax teacher
                    float sv = ea[q]*rA;
                    float tv = eb[q]*rB;
                    float dv = lp - lq;
                    int idx = (b*CC + c)*KK + k;   // reshape order of [B,C,K]
                    g_t[idx]=tv; g_s[idx]=sv; g_d[idx]=dv;
                    int i2 = (k*BB + b)*CC + c;
                    g_tk[i2]=tv; g_sk[i2]=sv;
                    int j = binOf(dv);
                    atomicAdd(&g_count[j], 1);
                    atomicAdd(&g_binT[j], tv);
                    atomicAdd(&g_binS[j], sv);
                    kl  += tv*dv;
                    tt  += tv*tv;
                    ssv += sv*sv;
                    tsv += tv*sv;
                    if (c == tg) atomicAdd(&g_ce, (double)(-lq));
                }
            }
            #pragma unroll
            for (int o=16;o;o>>=1){
                kl  += __shfl_xor_sync(0xffffffffu, kl,  o);
                tt  += __shfl_xor_sync(0xffffffffu, tt,  o);
                ssv += __shfl_xor_sync(0xffffffffu, ssv, o);
                tsv += __shfl_xor_sync(0xffffffffu, tsv, o);
            }
            if (lane==0){
                atomicAdd(&g_kl[k], (double)kl);
                atomicAdd(&g_tt, (double)tt);
                atomicAdd(&g_ss, (double)ssv);
                atomicAdd(&g_ts, (double)tsv);
            }
        }
    }
    gridBar();

    // ================= Phase B: block 0 scans bins; blocks 1..127 do Gram losses =================
    if (bid == 0){
        int base = tid*16;
        int cS = 0; float tS = 0.f, sS = 0.f;
        #pragma unroll
        for (int m=0;m<16;m++){
            cS += g_count[base+m];
            tS += g_binT[base+m];
            sS += g_binS[base+m];
        }
        shC[tid]=cS; shA[tid]=tS; shB[tid]=sS;
        __syncthreads();
        for (int off=1; off<NTHR; off<<=1){
            int   c = shC[tid]; float a = shA[tid], b2 = shB[tid];
            int cu=0; float au=0.f, bu=0.f;
            if (tid >= off){ cu=shC[tid-off]; au=shA[tid-off]; bu=shB[tid-off]; }
            __syncthreads();
            shC[tid]=c+cu; shA[tid]=a+au; shB[tid]=b2+bu;
            __syncthreads();
        }
        int   exC = tid ? shC[tid-1] : 0;
        float exT = tid ? shA[tid-1] : 0.f;
        float exS = tid ? shB[tid-1] : 0.f;
        #pragma unroll
        for (int m=0;m<16;m++){
            g_off[base+m]=exC; g_PT[base+m]=exT; g_PS[base+m]=exS;
            exC += g_count[base+m];
            exT += g_binT[base+m];
            exS += g_binS[base+m];
        }
        if (tid == NTHR-1){ g_off[NBINS]=exC; g_PT[NBINS]=exT; g_PS[NBINS]=exS; }
        __syncthreads();
    } else {
        // Gram 2x2 tiles: G (BxB) -> 5*32*32 tiles, H (CxC) -> 5*50*50 tiles
        const int NTG = KK*32*32;       // 5120
        const int NTH = KK*50*50;       // 12500
        int gid = (bid-1)*NTHR + tid;   // 127*256 = 32512 >= 17620
        float val = 0.f;
        if (gid < NTG){
            int k  = gid >> 10;
            int r  = gid & 1023;
            int i0 = (r >> 5) << 1;
            int j0 = (r & 31) << 1;
            const float* T = g_tk + k*BB*CC;
            const float* S = g_sk + k*BB*CC;
            float a00=0.f,a01=0.f,a10=0.f,a11=0.f;
            for (int c=0;c<CC;c++){
                float ti0=T[i0*CC+c],     ti1=T[(i0+1)*CC+c];
                float tj0=T[j0*CC+c],     tj1=T[(j0+1)*CC+c];
                float si0=S[i0*CC+c],     si1=S[(i0+1)*CC+c];
                float sj0=S[j0*CC+c],     sj1=S[(j0+1)*CC+c];
                a00 += ti0*tj0 - si0*sj0;
                a01 += ti0*tj1 - si0*sj1;
                a10 += ti1*tj0 - si1*sj0;
                a11 += ti1*tj1 - si1*sj1;
            }
            val = a00*a00 + a01*a01 + a10*a10 + a11*a11;
        } else if (gid < NTG + NTH){
            int u  = gid - NTG;
            int k  = u / 2500;
            int r  = u - k*2500;
            int i0 = (r / 50) * 2;
            int j0 = (r % 50) * 2;
            const float* T = g_tk + k*BB*CC;
            const float* S = g_sk + k*BB*CC;
            float a00=0.f,a01=0.f,a10=0.f,a11=0.f;
            for (int b2=0;b2<BB;b2++){
                const float* Tr = T + b2*CC;
                const float* Sr = S + b2*CC;
                float ti0=Tr[i0], ti1=Tr[i0+1];
                float tj0=Tr[j0], tj1=Tr[j0+1];
                float si0=Sr[i0], si1=Sr[i0+1];
                float sj0=Sr[j0], sj1=Sr[j0+1];
                a00 += ti0*tj0 - si0*sj0;
                a01 += ti0*tj1 - si0*sj1;
                a10 += ti1*tj0 - si1*sj0;
                a11 += ti1*tj1 - si1*sj1;
            }
            val = a00*a00 + a01*a01 + a10*a10 + a11*a11;
        }
        float r2 = blockSum(val, shR);
        if (tid==0) atomicAdd(&g_sub, (double)r2);
    }
    gridBar();

    // ================= Phase C: scatter into bin-sorted arrays =================
    {
        int id = bid*NTHR + tid;      // 128*256 = 32768 >= NN
        if (id < NN){
            float dv = g_d[id];
            int j = binOf(dv);
            int pos = g_off[j] + atomicAdd(&g_cur[j], 1);
            g_ds[pos]  = dv;
            g_tso[pos] = g_t[id];
            g_sso[pos] = g_s[id];
        }
    }
    gridBar();

    // ================= Phase D: L1 main reduction =================
    // L1 = sum_a [ t_a(2*P_t(a)-T) - s_a(2*P_s(a)-S) ], P via bin suffix + exact boundary bin
    {
        int id = bid*NTHR + tid;
        float contrib = 0.f;
        if (id < NN){
            float Ttot = g_PT[NBINS], Stot = g_PS[NBINS];
            float x = -g_d[id];
            int j = binOf(x);
            float pt = Ttot - g_PT[j+1];
            float ps = Stot - g_PS[j+1];
            int e0 = g_off[j], e1 = g_off[j+1];
            for (int m=e0; m<e1; ++m){
                if (g_ds[m] > x){ pt += g_tso[m]; ps += g_sso[m]; }
            }
            contrib = g_t[id]*(2.f*pt - Ttot) - g_s[id]*(2.f*ps - Stot);
        }
        float r2 = blockSum(contrib, shR);
        if (tid==0) atomicAdd(&g_l1, (double)r2);
    }
    gridBar();

    // ================= Phase E: final combine (block 0) + cleanup for next replay =================
    if (bid == 0){
        if (tid == 0){
            double ce = g_ce / (double)BB;
            double kd = 0.0;
            #pragma unroll
            for (int k=0;k<KK;k++){
                double T = (double)(k+1);
                kd += (g_kl[k] / (double)(BB*CC)) * (0.7*T*T) + ce * 0.3;
            }
            double tt=g_tt, ss2=g_ss, ts2=g_ts;
            double l2 = 0.00025*(tt*tt - 2.0*ts2*ts2 + ss2*ss2);
            out[0] = (float)(kd + 0.00025*g_l1 + l2 + g_sub);
            // zero scalar accumulators for next graph replay
            g_tt = 0.0; g_ss = 0.0; g_ts = 0.0;
            g_ce = 0.0; g_l1 = 0.0; g_sub = 0.0;
            #pragma unroll
            for (int k=0;k<KK;k++) g_kl[k] = 0.0;
        }
    } else {
        for (int j = (bid-1)*NTHR + tid; j < NBINS; j += (NBLK-1)*NTHR){
            g_count[j]=0; g_cur[j]=0; g_binT[j]=0.f; g_binS[j]=0.f;
        }
    }
}

// ---------------- launch ----------------
extern "C" void kernel_launch(void* const* d_in, const int* in_sizes, int n_in,
                              void* d_out, int out_size){
    (void)in_sizes; (void)n_in; (void)out_size;
    const float* ls  = (const float*)d_in[0];  // logits_student [64,100]
    const float* lt  = (const float*)d_in[1];  // logits_teacher [64,100]
    const int*   tgt = (const int*)  d_in[2];  // target [64]
    float* out = (float*)d_out;

    fused_kernel<<<NBLK, NTHR>>>(ls, lt, tgt, out);
}

// round 4
// speedup vs baseline: 1.4898x; 1.4898x over previous
#include <cuda_runtime.h>
#include <math.h>
#include <float.h>

#define BB 64
#define CC 100
#define KK 5
#define NN (BB*CC*KK)      // 32000
#define NBINS 65536
#define GRP   512          // bins per block in hierarchical scan
#define NGRP  128
#define NBLK  128
#define NTHR  256
#define DMINF (-32.0f)
#define INVWF 1024.0f      // NBINS / 64

// ---------------- device scratch (no allocs allowed) ----------------
__device__ float g_t[NN], g_s[NN], g_d[NN];
__device__ float g_tk[KK*BB*CC], g_sk[KK*BB*CC];   // [k][b][c]
__device__ float g_ds[NN], g_tso[NN], g_sso[NN];   // bin-sorted
__device__ int   g_count[NBINS], g_cur[NBINS];
__device__ float g_binT[NBINS], g_binS[NBINS];
__device__ int   g_off[NBINS];                     // group-local exclusive prefix
__device__ float g_PT[NBINS], g_PS[NBINS];
__device__ int   g_blkC[NGRP], g_blkOffC[NGRP];
__device__ float g_blkT[NGRP], g_blkOffT[NGRP];
__device__ float g_blkS[NGRP], g_blkOffS[NGRP];
__device__ float g_totT, g_totS;
__device__ double g_tt, g_ss, g_ts, g_kl[KK], g_ce, g_l1, g_sub;
__device__ volatile unsigned g_barGen;
__device__ unsigned g_barCnt;

__device__ __forceinline__ int binOf(float x){
    int j = (int)floorf((x - DMINF) * INVWF);
    return min(max(j, 0), NBINS-1);
}

__device__ __forceinline__ void gridBar(){
    __syncthreads();
    if (threadIdx.x == 0){
        unsigned gen = g_barGen;
        __threadfence();
        if (atomicAdd(&g_barCnt, 1u) == NBLK-1u){
            g_barCnt = 0u;
            __threadfence();
            g_barGen = gen + 1u;
        } else {
            while (g_barGen == gen) { __nanosleep(32); }
            __threadfence();
        }
    }
    __syncthreads();
}

__device__ __forceinline__ float blockSum(float v, float* shR){
    int lane = threadIdx.x & 31, w = threadIdx.x >> 5;
    #pragma unroll
    for (int o=16;o;o>>=1) v += __shfl_down_sync(0xffffffffu, v, o);
    if (lane==0) shR[w] = v;
    __syncthreads();
    float r = 0.f;
    if (threadIdx.x==0){
        #pragma unroll
        for (int i=0;i<NTHR/32;i++) r += shR[i];
    }
    __syncthreads();
    return r;   // valid on tid 0 only
}

__global__ void __launch_bounds__(NTHR)
fused_kernel(const float* __restrict__ ls, const float* __restrict__ lt,
             const int* __restrict__ tgt, float* __restrict__ out)
{
    __shared__ int   shC[NTHR];
    __shared__ float shA[NTHR], shB[NTHR];
    __shared__ float shR[NTHR/32];

    const int tid  = threadIdx.x;
    const int bid  = blockIdx.x;
    const int lane = tid & 31;
    const int wid  = tid >> 5;

    // ============ Phase A: softmax + KD + L2 dots + fine histogram ============
    {
        int gw = bid*(NTHR/32) + wid;          // global warp id, BB*KK=320 tasks
        if (gw < BB*KK){
            int b = gw / KK, k = gw % KK;
            float invT = 1.0f / (float)(k+1);
            float av[4], bv[4];
            float amax = -FLT_MAX, bmax = -FLT_MAX;
            #pragma unroll
            for (int q=0;q<4;q++){
                int c = lane + 32*q;
                bool ok = c < CC;
                av[q] = ok ? ls[b*CC+c]*invT : -FLT_MAX;
                bv[q] = ok ? lt[b*CC+c]*invT : -FLT_MAX;
                amax = fmaxf(amax, av[q]);
                bmax = fmaxf(bmax, bv[q]);
            }
            #pragma unroll
            for (int o=16;o;o>>=1){
                amax = fmaxf(amax, __shfl_xor_sync(0xffffffffu, amax, o));
                bmax = fmaxf(bmax, __shfl_xor_sync(0xffffffffu, bmax, o));
            }
            float ea[4], eb[4], sumA = 0.f, sumB = 0.f;
            #pragma unroll
            for (int q=0;q<4;q++){
                int c = lane + 32*q;
                ea[q] = (c<CC) ? expf(av[q]-amax) : 0.f;
                eb[q] = (c<CC) ? expf(bv[q]-bmax) : 0.f;
                sumA += ea[q]; sumB += eb[q];
            }
            #pragma unroll
            for (int o=16;o;o>>=1){
                sumA += __shfl_xor_sync(0xffffffffu, sumA, o);
                sumB += __shfl_xor_sync(0xffffffffu, sumB, o);
            }
            float lA = logf(sumA), lB = logf(sumB);
            float rA = 1.f/sumA, rB = 1.f/sumB;
            int tg = (k==0) ? tgt[b] : -1;
            float kl=0.f, tt=0.f, ssv=0.f, tsv=0.f;
            #pragma unroll
            for (int q=0;q<4;q++){
                int c = lane + 32*q;
                if (c < CC){
                    float lq = av[q]-amax-lA;
                    float lp = bv[q]-bmax-lB;
                    float sv = ea[q]*rA;
                    float tv = eb[q]*rB;
                    float dv = lp - lq;
                    int idx = (b*CC + c)*KK + k;
                    g_t[idx]=tv; g_s[idx]=sv; g_d[idx]=dv;
                    int i2 = (k*BB + b)*CC + c;
                    g_tk[i2]=tv; g_sk[i2]=sv;
                    int j = binOf(dv);
                    atomicAdd(&g_count[j], 1);
                    atomicAdd(&g_binT[j], tv);
                    atomicAdd(&g_binS[j], sv);
                    kl  += tv*dv;
                    tt  += tv*tv;
                    ssv += sv*sv;
                    tsv += tv*sv;
                    if (c == tg) atomicAdd(&g_ce, (double)(-lq));
                }
            }
            #pragma unroll
            for (int o=16;o;o>>=1){
                kl  += __shfl_xor_sync(0xffffffffu, kl,  o);
                tt  += __shfl_xor_sync(0xffffffffu, tt,  o);
                ssv += __shfl_xor_sync(0xffffffffu, ssv, o);
                tsv += __shfl_xor_sync(0xffffffffu, tsv, o);
            }
            if (lane==0){
                atomicAdd(&g_kl[k], (double)kl);
                atomicAdd(&g_tt, (double)tt);
                atomicAdd(&g_ss, (double)ssv);
                atomicAdd(&g_ts, (double)tsv);
            }
        }
    }
    gridBar();

    // ============ Phase B1: per-group (512 bins) local exclusive scan ============
    {
        int base = bid*GRP + tid*2;
        int   c0 = g_count[base], c1 = g_count[base+1];
        float t0 = g_binT[base],  t1 = g_binT[base+1];
        float s0 = g_binS[base],  s1 = g_binS[base+1];
        shC[tid]=c0+c1; shA[tid]=t0+t1; shB[tid]=s0+s1;
        __syncthreads();
        for (int off=1; off<NTHR; off<<=1){
            int c = shC[tid]; float a = shA[tid], b2 = shB[tid];
            int cu=0; float au=0.f, bu=0.f;
            if (tid >= off){ cu=shC[tid-off]; au=shA[tid-off]; bu=shB[tid-off]; }
            __syncthreads();
            shC[tid]=c+cu; shA[tid]=a+au; shB[tid]=b2+bu;
            __syncthreads();
        }
        int   exC = tid ? shC[tid-1] : 0;
        float exT = tid ? shA[tid-1] : 0.f;
        float exS = tid ? shB[tid-1] : 0.f;
        g_off[base]  =exC;    g_PT[base]  =exT;    g_PS[base]  =exS;
        g_off[base+1]=exC+c0; g_PT[base+1]=exT+t0; g_PS[base+1]=exS+s0;
        if (tid == NTHR-1){
            g_blkC[bid]=shC[NTHR-1]; g_blkT[bid]=shA[NTHR-1]; g_blkS[bid]=shB[NTHR-1];
        }
    }
    gridBar();

    // ============ Phase B2: block 0 scans group totals; others do Gram ============
    if (bid == 0){
        int   c = (tid < NGRP) ? g_blkC[tid] : 0;
        float a = (tid < NGRP) ? g_blkT[tid] : 0.f;
        float s = (tid < NGRP) ? g_blkS[tid] : 0.f;
        shC[tid]=c; shA[tid]=a; shB[tid]=s;
        __syncthreads();
        for (int off=1; off<NTHR; off<<=1){
            int cv = shC[tid]; float av2 = shA[tid], sv2 = shB[tid];
            int cu=0; float au=0.f, su=0.f;
            if (tid >= off){ cu=shC[tid-off]; au=shA[tid-off]; su=shB[tid-off]; }
            __syncthreads();
            shC[tid]=cv+cu; shA[tid]=av2+au; shB[tid]=sv2+su;
            __syncthreads();
        }
        if (tid < NGRP){
            g_blkOffC[tid] = tid ? shC[tid-1] : 0;
            g_blkOffT[tid] = tid ? shA[tid-1] : 0.f;
            g_blkOffS[tid] = tid ? shB[tid-1] : 0.f;
        }
        if (tid == NGRP-1){ g_totT = shA[tid]; g_totS = shB[tid]; }
        __syncthreads();
    } else {
        // Gram 2x2 tiles: G (BxB) -> 5*32*32, H (CxC) -> 5*50*50 tiles
        const int NTG = KK*32*32;       // 5120
        const int NTH = KK*50*50;       // 12500
        int gid = (bid-1)*NTHR + tid;   // 127*256 = 32512 >= 17620
        float val = 0.f;
        if (gid < NTG){
            int k  = gid >> 10;
            int r  = gid & 1023;
            int i0 = (r >> 5) << 1;
            int j0 = (r & 31) << 1;
            const float* T = g_tk + k*BB*CC;
            const float* S = g_sk + k*BB*CC;
            float a00=0.f,a01=0.f,a10=0.f,a11=0.f;
            for (int c=0;c<CC;c++){
                float ti0=T[i0*CC+c],     ti1=T[(i0+1)*CC+c];
                float tj0=T[j0*CC+c],     tj1=T[(j0+1)*CC+c];
                float si0=S[i0*CC+c],     si1=S[(i0+1)*CC+c];
                float sj0=S[j0*CC+c],     sj1=S[(j0+1)*CC+c];
                a00 += ti0*tj0 - si0*sj0;
                a01 += ti0*tj1 - si0*sj1;
                a10 += ti1*tj0 - si1*sj0;
                a11 += ti1*tj1 - si1*sj1;
            }
            val = a00*a00 + a01*a01 + a10*a10 + a11*a11;
        } else if (gid < NTG + NTH){
            int u  = gid - NTG;
            int k  = u / 2500;
            int r  = u - k*2500;
            int i0 = (r / 50) * 2;
            int j0 = (r % 50) * 2;
            const float* T = g_tk + k*BB*CC;
            const float* S = g_sk + k*BB*CC;
            float a00=0.f,a01=0.f,a10=0.f,a11=0.f;
            for (int b2=0;b2<BB;b2++){
                const float* Tr = T + b2*CC;
                const float* Sr = S + b2*CC;
                float ti0=Tr[i0], ti1=Tr[i0+1];
                float tj0=Tr[j0], tj1=Tr[j0+1];
                float si0=Sr[i0], si1=Sr[i0+1];
                float sj0=Sr[j0], sj1=Sr[j0+1];
                a00 += ti0*tj0 - si0*sj0;
                a01 += ti0*tj1 - si0*sj1;
                a10 += ti1*tj0 - si1*sj0;
                a11 += ti1*tj1 - si1*sj1;
            }
            val = a00*a00 + a01*a01 + a10*a10 + a11*a11;
        }
        float r2 = blockSum(val, shR);
        if (tid==0) atomicAdd(&g_sub, (double)r2);
    }
    gridBar();

    // ============ Phase C: scatter into bin-sorted arrays ============
    {
        int id = bid*NTHR + tid;
        if (id < NN){
            float dv = g_d[id];
            int j = binOf(dv);
            int pos = g_blkOffC[j>>9] + g_off[j] + atomicAdd(&g_cur[j], 1);
            g_ds[pos]  = dv;
            g_tso[pos] = g_t[id];
            g_sso[pos] = g_s[id];
        }
    }
    gridBar();

    // ============ Phase D: L1 main reduction ============
    // L1 = sum_a [ t_a(2*P_t(a)-T) - s_a(2*P_s(a)-S) ]
    // P_t(a) = sum of t_b over { d_b > -d_a } = Ttot - inclPrefix(bin) + exact in-bin scan
    {
        int id = bid*NTHR + tid;
        float contrib = 0.f;
        if (id < NN){
            float Ttot = g_totT, Stot = g_totS;
            float x = -g_d[id];
            int j = binOf(x);
            int g = j >> 9;
            int cnt = g_count[j];
            float inclT = g_blkOffT[g] + g_PT[j] + g_binT[j];
            float inclS = g_blkOffS[g] + g_PS[j] + g_binS[j];
            float pt = Ttot - inclT;
            float ps = Stot - inclS;
            int e0 = g_blkOffC[g] + g_off[j];
            int e1 = e0 + cnt;
            for (int m=e0; m<e1; ++m){
                if (g_ds[m] > x){ pt += g_tso[m]; ps += g_sso[m]; }
            }
            contrib = g_t[id]*(2.f*pt - Ttot) - g_s[id]*(2.f*ps - Stot);
        }
        float r2 = blockSum(contrib, shR);
        if (tid==0) atomicAdd(&g_l1, (double)r2);
    }
    gridBar();

    // ============ Phase E: final combine + cleanup for next graph replay ============
    {
        // zero fine-histogram state (off/PT/PS/blk* are fully rewritten each call)
        for (int j = bid*NTHR + tid; j < NBINS; j += NBLK*NTHR){
            g_count[j]=0; g_cur[j]=0; g_binT[j]=0.f; g_binS[j]=0.f;
        }
        if (bid == 0 && tid == 0){
            double ce = g_ce / (double)BB;
            double kd = 0.0;
            #pragma unroll
            for (int k=0;k<KK;k++){
                double T = (double)(k+1);
                kd += (g_kl[k] / (double)(BB*CC)) * (0.7*T*T) + ce * 0.3;
            }
            double tt=g_tt, ss2=g_ss, ts2=g_ts;
            double l2 = 0.00025*(tt*tt - 2.0*ts2*ts2 + ss2*ss2);
            out[0] = (float)(kd + 0.00025*g_l1 + l2 + g_sub);
            g_tt = 0.0; g_ss = 0.0; g_ts = 0.0;
            g_ce = 0.0; g_l1 = 0.0; g_sub = 0.0;
            #pragma unroll
            for (int k=0;k<KK;k++) g_kl[k] = 0.0;
        }
    }
}

// ---------------- launch ----------------
extern "C" void kernel_launch(void* const* d_in, const int* in_sizes, int n_in,
                              void* d_out, int out_size){
    (void)in_sizes; (void)n_in; (void)out_size;
    const float* ls  = (const float*)d_in[0];  // logits_student [64,100]
    const float* lt  = (const float*)d_in[1];  // logits_teacher [64,100]
    const int*   tgt = (const int*)  d_in[2];  // target [64]
    float* out = (float*)d_out;

    fused_kernel<<<NBLK, NTHR>>>(ls, lt, tgt, out);
}

// round 5
// speedup vs baseline: 1.6428x; 1.1027x over previous
#include <cuda_runtime.h>
#include <math.h>
#include <float.h>

#define BB 64
#define CC 100
#define KK 5
#define NN (BB*CC*KK)      // 32000
#define NBINS 65536
#define GRP   512
#define NGRP  128
#define NBLK  128
#define NTHR  256
#define DMINF (-32.0f)
#define INVWF 1024.0f      // NBINS / 64

// ---------------- device scratch (no allocs allowed) ----------------
__device__ float4 g_pack[NN];          // (t, s, d, 0)
__device__ float4 g_sorted[NN];        // (d, t, s, 0) bin-sorted
__device__ float4 g_binPack[NBINS];    // (inclT_loc, inclS_loc, offExc_loc, count)
__device__ float4 g_agg[NGRP];         // (aggT, aggS, aggC, flag)
__device__ float  g_tk[KK*BB*CC], g_sk[KK*BB*CC];   // [k][b][c]
__device__ int    g_count[NBINS], g_cur[NBINS];
__device__ float  g_binT[NBINS], g_binS[NBINS];
__device__ double g_tt, g_ss, g_ts, g_kl[KK], g_ce, g_l1, g_sub;
__device__ volatile unsigned g_barGen;
__device__ unsigned g_barCnt;

__device__ __forceinline__ int binOf(float x){
    int j = (int)floorf((x - DMINF) * INVWF);
    return min(max(j, 0), NBINS-1);
}

__device__ __forceinline__ float4 ldvol4(const float4* p){
    float4 v;
    asm volatile("ld.volatile.global.v4.f32 {%0,%1,%2,%3}, [%4];"
                 : "=f"(v.x),"=f"(v.y),"=f"(v.z),"=f"(v.w) : "l"(p));
    return v;
}
__device__ __forceinline__ void stvol4(float4* p, float4 v){
    asm volatile("st.volatile.global.v4.f32 [%0], {%1,%2,%3,%4};"
                 :: "l"(p), "f"(v.x),"f"(v.y),"f"(v.z),"f"(v.w) : "memory");
}

__device__ __forceinline__ void gridBar(){
    __syncthreads();
    if (threadIdx.x == 0){
        unsigned gen = g_barGen;
        __threadfence();
        if (atomicAdd(&g_barCnt, 1u) == NBLK-1u){
            g_barCnt = 0u;
            __threadfence();
            g_barGen = gen + 1u;
        } else {
            while (g_barGen == gen) { __nanosleep(32); }
            __threadfence();
        }
    }
    __syncthreads();
}

__device__ __forceinline__ float blockSum(float v, float* shR){
    int lane = threadIdx.x & 31, w = threadIdx.x >> 5;
    #pragma unroll
    for (int o=16;o;o>>=1) v += __shfl_down_sync(0xffffffffu, v, o);
    if (lane==0) shR[w] = v;
    __syncthreads();
    float r = 0.f;
    if (threadIdx.x==0){
        #pragma unroll
        for (int i=0;i<NTHR/32;i++) r += shR[i];
    }
    __syncthreads();
    return r;   // valid on tid 0 only
}

__global__ void __launch_bounds__(NTHR)
fused_kernel(const float* __restrict__ ls, const float* __restrict__ lt,
             const int* __restrict__ tgt, float* __restrict__ out)
{
    __shared__ float shC[NTHR], shA[NTHR], shB[NTHR];
    __shared__ float shOffC[NGRP], shOffT[NGRP], shOffS[NGRP];
    __shared__ float shTotT, shTotS;
    __shared__ float shR[NTHR/32];

    const int tid  = threadIdx.x;
    const int bid  = blockIdx.x;
    const int lane = tid & 31;
    const int wid  = tid >> 5;

    // ============ Phase A: softmax + KD + L2 dots + fine histogram ============
    {
        int gw = bid*(NTHR/32) + wid;          // BB*KK = 320 warp tasks
        if (gw < BB*KK){
            int b = gw / KK, k = gw % KK;
            float invT = 1.0f / (float)(k+1);
            float av[4], bv[4];
            float amax = -FLT_MAX, bmax = -FLT_MAX;
            #pragma unroll
            for (int q=0;q<4;q++){
                int c = lane + 32*q;
                bool ok = c < CC;
                av[q] = ok ? ls[b*CC+c]*invT : -FLT_MAX;
                bv[q] = ok ? lt[b*CC+c]*invT : -FLT_MAX;
                amax = fmaxf(amax, av[q]);
                bmax = fmaxf(bmax, bv[q]);
            }
            #pragma unroll
            for (int o=16;o;o>>=1){
                amax = fmaxf(amax, __shfl_xor_sync(0xffffffffu, amax, o));
                bmax = fmaxf(bmax, __shfl_xor_sync(0xffffffffu, bmax, o));
            }
            float ea[4], eb[4], sumA = 0.f, sumB = 0.f;
            #pragma unroll
            for (int q=0;q<4;q++){
                int c = lane + 32*q;
                ea[q] = (c<CC) ? expf(av[q]-amax) : 0.f;
                eb[q] = (c<CC) ? expf(bv[q]-bmax) : 0.f;
                sumA += ea[q]; sumB += eb[q];
            }
            #pragma unroll
            for (int o=16;o;o>>=1){
                sumA += __shfl_xor_sync(0xffffffffu, sumA, o);
                sumB += __shfl_xor_sync(0xffffffffu, sumB, o);
            }
            float lA = logf(sumA), lB = logf(sumB);
            float rA = 1.f/sumA, rB = 1.f/sumB;
            int tg = (k==0) ? tgt[b] : -1;
            float kl=0.f, tt=0.f, ssv=0.f, tsv=0.f;
            #pragma unroll
            for (int q=0;q<4;q++){
                int c = lane + 32*q;
                if (c < CC){
                    float lq = av[q]-amax-lA;
                    float lp = bv[q]-bmax-lB;
                    float sv = ea[q]*rA;
                    float tv = eb[q]*rB;
                    float dv = lp - lq;
                    int idx = (b*CC + c)*KK + k;
                    g_pack[idx] = make_float4(tv, sv, dv, 0.f);
                    int i2 = (k*BB + b)*CC + c;
                    g_tk[i2]=tv; g_sk[i2]=sv;
                    int j = binOf(dv);
                    atomicAdd(&g_count[j], 1);
                    atomicAdd(&g_binT[j], tv);
                    atomicAdd(&g_binS[j], sv);
                    kl  += tv*dv;
                    tt  += tv*tv;
                    ssv += sv*sv;
                    tsv += tv*sv;
                    if (c == tg) atomicAdd(&g_ce, (double)(-lq));
                }
            }
            #pragma unroll
            for (int o=16;o;o>>=1){
                kl  += __shfl_xor_sync(0xffffffffu, kl,  o);
                tt  += __shfl_xor_sync(0xffffffffu, tt,  o);
                ssv += __shfl_xor_sync(0xffffffffu, ssv, o);
                tsv += __shfl_xor_sync(0xffffffffu, tsv, o);
            }
            if (lane==0){
                atomicAdd(&g_kl[k], (double)kl);
                atomicAdd(&g_tt, (double)tt);
                atomicAdd(&g_ss, (double)ssv);
                atomicAdd(&g_ts, (double)tsv);
            }
        }
    }
    gridBar();

    // ============ Phase B: local scan + flag-published group prefix + scatter + Gram ============
    {
        // --- local exclusive scan of this block's 512-bin group ---
        int b0 = bid*GRP + tid*2;
        float c0 = (float)g_count[b0], c1 = (float)g_count[b0+1];
        float t0 = g_binT[b0], t1 = g_binT[b0+1];
        float s0 = g_binS[b0], s1 = g_binS[b0+1];
        shC[tid]=c0+c1; shA[tid]=t0+t1; shB[tid]=s0+s1;
        __syncthreads();
        for (int off=1; off<NTHR; off<<=1){
            float vC=shC[tid], vT=shA[tid], vS=shB[tid];
            float uC=0.f,uT=0.f,uS=0.f;
            if (tid>=off){ uC=shC[tid-off]; uT=shA[tid-off]; uS=shB[tid-off]; }
            __syncthreads();
            shC[tid]=vC+uC; shA[tid]=vT+uT; shB[tid]=vS+uS;
            __syncthreads();
        }
        float exC = tid? shC[tid-1]:0.f;
        float exT = tid? shA[tid-1]:0.f;
        float exS = tid? shB[tid-1]:0.f;
        g_binPack[b0]   = make_float4(exT+t0,    exS+s0,    exC,    c0);
        g_binPack[b0+1] = make_float4(exT+t0+t1, exS+s0+s1, exC+c0, c1);
        float aggC=shC[NTHR-1], aggT=shA[NTHR-1], aggS=shB[NTHR-1];
        __syncthreads();                 // all binPack stores issued block-wide
        if (tid==NTHR-1){
            __threadfence();             // make block's stores globally visible, then flag
            stvol4(&g_agg[bid], make_float4(aggT, aggS, aggC, 1.0f));
        }
        // --- every block gathers all 128 group aggregates (flag in same 16B) ---
        if (tid < NGRP){
            float4 a;
            for(;;){ a = ldvol4(&g_agg[tid]); if (a.w != 0.f) break; __nanosleep(32); }
            shC[tid]=a.z; shA[tid]=a.x; shB[tid]=a.y;
        }
        if (tid < NGRP) __threadfence();
        __syncthreads();
        for (int off=1; off<NGRP; off<<=1){
            float vC=0.f,vT=0.f,vS=0.f,uC=0.f,uT=0.f,uS=0.f;
            if (tid < NGRP){
                vC=shC[tid]; vT=shA[tid]; vS=shB[tid];
                if (tid>=off){ uC=shC[tid-off]; uT=shA[tid-off]; uS=shB[tid-off]; }
            }
            __syncthreads();
            if (tid < NGRP){ shC[tid]=vC+uC; shA[tid]=vT+uT; shB[tid]=vS+uS; }
            __syncthreads();
        }
        if (tid < NGRP){
            shOffC[tid] = tid? shC[tid-1] : 0.f;
            shOffT[tid] = tid? shA[tid-1] : 0.f;
            shOffS[tid] = tid? shB[tid-1] : 0.f;
        }
        if (tid==0){ shTotT = shA[NGRP-1]; shTotS = shB[NGRP-1]; }
        __syncthreads();

        // --- scatter this block's elements into bin-sorted order ---
        int id = bid*NTHR + tid;
        if (id < NN){
            float4 p = g_pack[id];
            int j = binOf(p.z);
            int g = j >> 9;
            float4 bp = g_binPack[j];
            int pos = (int)shOffC[g] + (int)bp.z + atomicAdd(&g_cur[j], 1);
            g_sorted[pos] = make_float4(p.z, p.x, p.y, 0.f);
        }

        // --- Gram sub losses (2x2 tiles), all blocks ---
        const int NTG = KK*32*32;       // 5120
        const int NTH = KK*50*50;       // 12500
        int gid = bid*NTHR + tid;       // 32768 >= 17620
        float val = 0.f;
        if (gid < NTG){
            int k  = gid >> 10;
            int r  = gid & 1023;
            int i0 = (r >> 5) << 1;
            int j0 = (r & 31) << 1;
            const float* T = g_tk + k*BB*CC;
            const float* S = g_sk + k*BB*CC;
            float a00=0.f,a01=0.f,a10=0.f,a11=0.f;
            for (int c=0;c<CC;c++){
                float ti0=T[i0*CC+c],     ti1=T[(i0+1)*CC+c];
                float tj0=T[j0*CC+c],     tj1=T[(j0+1)*CC+c];
                float si0=S[i0*CC+c],     si1=S[(i0+1)*CC+c];
                float sj0=S[j0*CC+c],     sj1=S[(j0+1)*CC+c];
                a00 += ti0*tj0 - si0*sj0;
                a01 += ti0*tj1 - si0*sj1;
                a10 += ti1*tj0 - si1*sj0;
                a11 += ti1*tj1 - si1*sj1;
            }
            val = a00*a00 + a01*a01 + a10*a10 + a11*a11;
        } else if (gid < NTG + NTH){
            int u  = gid - NTG;
            int k  = u / 2500;
            int r  = u - k*2500;
            int i0 = (r / 50) * 2;
            int j0 = (r % 50) * 2;
            const float* T = g_tk + k*BB*CC;
            const float* S = g_sk + k*BB*CC;
            float a00=0.f,a01=0.f,a10=0.f,a11=0.f;
            for (int b2=0;b2<BB;b2++){
                const float* Tr = T + b2*CC;
                const float* Sr = S + b2*CC;
                float ti0=Tr[i0], ti1=Tr[i0+1];
                float tj0=Tr[j0], tj1=Tr[j0+1];
                float si0=Sr[i0], si1=Sr[i0+1];
                float sj0=Sr[j0], sj1=Sr[j0+1];
                a00 += ti0*tj0 - si0*sj0;
                a01 += ti0*tj1 - si0*sj1;
                a10 += ti1*tj0 - si1*sj0;
                a11 += ti1*tj1 - si1*sj1;
            }
            val = a00*a00 + a01*a01 + a10*a10 + a11*a11;
        }
        float r2 = blockSum(val, shR);
        if (tid==0) atomicAdd(&g_sub, (double)r2);
    }
    gridBar();

    // ============ Phase D: L1 main reduction + overlapped cleanup ============
    {
        int id = bid*NTHR + tid;
        float contrib = 0.f;
        if (id < NN){
            float4 p = g_pack[id];              // t=x, s=y, d=z
            float Ttot = shTotT, Stot = shTotS;
            float x = -p.z;
            int j = binOf(x);
            int g = j >> 9;
            float4 bp = g_binPack[j];           // inclT, inclS, offExc, count
            float pt = Ttot - (shOffT[g] + bp.x);
            float ps = Stot - (shOffS[g] + bp.y);
            int e0 = (int)shOffC[g] + (int)bp.z;
            int cnt = (int)bp.w;
            for (int m=e0; m<e0+cnt; ++m){
                float4 e = g_sorted[m];         // d, t, s
                if (e.x > x){ pt += e.y; ps += e.z; }
            }
            contrib = p.x*(2.f*pt - Ttot) - p.y*(2.f*ps - Stot);
        }
        float r2 = blockSum(contrib, shR);
        if (tid==0) atomicAdd(&g_l1, (double)r2);

        // cleanup for next graph replay (none of these are read again this call)
        for (int j2 = bid*NTHR + tid; j2 < NBINS; j2 += NBLK*NTHR){
            g_count[j2]=0; g_cur[j2]=0; g_binT[j2]=0.f; g_binS[j2]=0.f;
        }
        if (bid==0 && tid<NGRP) g_agg[tid] = make_float4(0.f,0.f,0.f,0.f);
    }
    gridBar();

    // ============ Phase E: final combine (block 0) ============
    if (bid == 0 && tid == 0){
        double ce = g_ce / (double)BB;
        double kd = 0.0;
        #pragma unroll
        for (int k=0;k<KK;k++){
            double T = (double)(k+1);
            kd += (g_kl[k] / (double)(BB*CC)) * (0.7*T*T) + ce * 0.3;
        }
        double tt=g_tt, ss2=g_ss, ts2=g_ts;
        double l2 = 0.00025*(tt*tt - 2.0*ts2*ts2 + ss2*ss2);
        out[0] = (float)(kd + 0.00025*g_l1 + l2 + g_sub);
        g_tt = 0.0; g_ss = 0.0; g_ts = 0.0;
        g_ce = 0.0; g_l1 = 0.0; g_sub = 0.0;
        #pragma unroll
        for (int k=0;k<KK;k++) g_kl[k] = 0.0;
    }
}

// ---------------- launch ----------------
extern "C" void kernel_launch(void* const* d_in, const int* in_sizes, int n_in,
                              void* d_out, int out_size){
    (void)in_sizes; (void)n_in; (void)out_size;
    const float* ls  = (const float*)d_in[0];  // logits_student [64,100]
    const float* lt  = (const float*)d_in[1];  // logits_teacher [64,100]
    const int*   tgt = (const int*)  d_in[2];  // target [64]
    float* out = (float*)d_out;

    fused_kernel<<<NBLK, NTHR>>>(ls, lt, tgt, out);
}

// round 6
// speedup vs baseline: 1.7092x; 1.0405x over previous
#include <cuda_runtime.h>
#include <math.h>
#include <float.h>

#define BB 64
#define CC 100
#define KK 5
#define NN (BB*CC*KK)      // 32000
#define NBINS 65536
#define NLB 64             // Team L blocks (L1 chain)
#define NGB 64             // Team G blocks (Gram)
#define GRPL (NBINS/NLB)   // 1024 bins per L block
#define NBLK 128
#define NTHR 256
#define NPB (NN/NLB)       // 500 elements per L block
#define NAB 40             // blocks active in Phase A (320 warp tasks / 8)
#define DMINF (-32.0f)
#define INVWF 1024.0f      // NBINS / 64

// ---------------- device scratch (no allocs allowed) ----------------
__device__ float4 g_pack[NN];          // (t, s, d, 0)
__device__ float4 g_sorted[NN];        // (d, t, s, 0) bin-sorted
__device__ float4 g_hist[NBINS];       // (count, sumT, sumS, 0) via float atomics
__device__ float4 g_binPack[NBINS];    // (inclT_loc, inclS_loc, offExcC_loc, count)
__device__ float4 g_aggL[NLB];         // (aggT, aggS, aggC, flag)
__device__ float4 g_aflag[NAB];        // Phase-A completion flags
__device__ int    g_cur[NBINS];
__device__ float  g_tk[KK*BB*CC], g_sk[KK*BB*CC];   // [k][b][c]
__device__ double g_tt, g_ss, g_ts, g_kl[KK], g_ce, g_l1, g_sub;
__device__ unsigned g_done;
__device__ volatile unsigned g_barLGen;
__device__ unsigned g_barLCnt;

__device__ __forceinline__ int binOf(float x){
    int j = (int)floorf((x - DMINF) * INVWF);
    return min(max(j, 0), NBINS-1);
}
__device__ __forceinline__ float4 ldvol4(const float4* p){
    float4 v;
    asm volatile("ld.volatile.global.v4.f32 {%0,%1,%2,%3}, [%4];"
                 : "=f"(v.x),"=f"(v.y),"=f"(v.z),"=f"(v.w) : "l"(p));
    return v;
}
__device__ __forceinline__ void stvol4(float4* p, float4 v){
    asm volatile("st.volatile.global.v4.f32 [%0], {%1,%2,%3,%4};"
                 :: "l"(p), "f"(v.x),"f"(v.y),"f"(v.z),"f"(v.w) : "memory");
}

// Team L barrier (64 blocks), generation-based, replay-safe
__device__ __forceinline__ void teamBarL(){
    __threadfence();
    __syncthreads();
    if (threadIdx.x == 0){
        unsigned gen = g_barLGen;
        if (atomicAdd(&g_barLCnt, 1u) == NLB-1u){
            g_barLCnt = 0u;
            __threadfence();
            g_barLGen = gen + 1u;
        } else {
            while (g_barLGen == gen) { __nanosleep(32); }
            __threadfence();
        }
    }
    __syncthreads();
}

__device__ __forceinline__ float blockSum(float v, float* shR){
    int lane = threadIdx.x & 31, w = threadIdx.x >> 5;
    #pragma unroll
    for (int o=16;o;o>>=1) v += __shfl_down_sync(0xffffffffu, v, o);
    if (lane==0) shR[w] = v;
    __syncthreads();
    float r = 0.f;
    if (threadIdx.x==0){
        #pragma unroll
        for (int i=0;i<NTHR/32;i++) r += shR[i];
    }
    __syncthreads();
    return r;   // valid on tid 0 only
}

__global__ void __launch_bounds__(NTHR)
fused_kernel(const float* __restrict__ ls, const float* __restrict__ lt,
             const int* __restrict__ tgt, float* __restrict__ out)
{
    __shared__ float shC[NTHR], shA[NTHR], shB[NTHR];
    __shared__ float shOffC[NLB], shOffT[NLB], shOffS[NLB];
    __shared__ float shTotT, shTotS;
    __shared__ float shR[NTHR/32];

    const int tid  = threadIdx.x;
    const int bid  = blockIdx.x;
    const int lane = tid & 31;
    const int wid  = tid >> 5;

    // ============ Phase A: softmax + KD + L2 dots + histogram (blocks 0..39) ============
    if (bid < NAB){
        int gw = bid*(NTHR/32) + wid;          // always < 320
        int b = gw / KK, k = gw % KK;
        float invT = 1.0f / (float)(k+1);
        float av[4], bv[4];
        float amax = -FLT_MAX, bmax = -FLT_MAX;
        #pragma unroll
        for (int q=0;q<4;q++){
            int c = lane + 32*q;
            bool ok = c < CC;
            av[q] = ok ? ls[b*CC+c]*invT : -FLT_MAX;
            bv[q] = ok ? lt[b*CC+c]*invT : -FLT_MAX;
            amax = fmaxf(amax, av[q]);
            bmax = fmaxf(bmax, bv[q]);
        }
        #pragma unroll
        for (int o=16;o;o>>=1){
            amax = fmaxf(amax, __shfl_xor_sync(0xffffffffu, amax, o));
            bmax = fmaxf(bmax, __shfl_xor_sync(0xffffffffu, bmax, o));
        }
        float ea[4], eb[4], sumA = 0.f, sumB = 0.f;
        #pragma unroll
        for (int q=0;q<4;q++){
            int c = lane + 32*q;
            ea[q] = (c<CC) ? expf(av[q]-amax) : 0.f;
            eb[q] = (c<CC) ? expf(bv[q]-bmax) : 0.f;
            sumA += ea[q]; sumB += eb[q];
        }
        #pragma unroll
        for (int o=16;o;o>>=1){
            sumA += __shfl_xor_sync(0xffffffffu, sumA, o);
            sumB += __shfl_xor_sync(0xffffffffu, sumB, o);
        }
        float lA = logf(sumA), lB = logf(sumB);
        float rA = 1.f/sumA, rB = 1.f/sumB;
        int tg = (k==0) ? tgt[b] : -1;
        float kl=0.f, tt=0.f, ssv=0.f, tsv=0.f;
        #pragma unroll
        for (int q=0;q<4;q++){
            int c = lane + 32*q;
            if (c < CC){
                float lq = av[q]-amax-lA;
                float lp = bv[q]-bmax-lB;
                float sv = ea[q]*rA;
                float tv = eb[q]*rB;
                float dv = lp - lq;
                int idx = (b*CC + c)*KK + k;
                g_pack[idx] = make_float4(tv, sv, dv, 0.f);
                int i2 = (k*BB + b)*CC + c;
                g_tk[i2]=tv; g_sk[i2]=sv;
                int j = binOf(dv);
                atomicAdd(&g_hist[j].x, 1.0f);
                atomicAdd(&g_hist[j].y, tv);
                atomicAdd(&g_hist[j].z, sv);
                kl  += tv*dv;
                tt  += tv*tv;
                ssv += sv*sv;
                tsv += tv*sv;
                if (c == tg) atomicAdd(&g_ce, (double)(-lq));
            }
        }
        #pragma unroll
        for (int o=16;o;o>>=1){
            kl  += __shfl_xor_sync(0xffffffffu, kl,  o);
            tt  += __shfl_xor_sync(0xffffffffu, tt,  o);
            ssv += __shfl_xor_sync(0xffffffffu, ssv, o);
            tsv += __shfl_xor_sync(0xffffffffu, tsv, o);
        }
        if (lane==0){
            atomicAdd(&g_kl[k], (double)kl);
            atomicAdd(&g_tt, (double)tt);
            atomicAdd(&g_ss, (double)ssv);
            atomicAdd(&g_ts, (double)tsv);
        }
        __threadfence();
        __syncthreads();
        if (tid==0) stvol4(&g_aflag[bid], make_float4(0.f,0.f,0.f,1.f));
    }

    // ---- all blocks wait for Phase A completion (40 flags) ----
    if (tid < NAB){
        for(;;){ float4 a = ldvol4(&g_aflag[tid]); if (a.w != 0.f) break; __nanosleep(32); }
    }
    __threadfence();
    __syncthreads();

    if (bid < NLB){
        // =================== TEAM L: bin scan -> scatter -> L1 ===================
        // --- local exclusive scan of this block's 1024-bin group (4 bins/thread) ---
        int base = bid*GRPL + tid*4;
        float4 h0=g_hist[base], h1=g_hist[base+1], h2=g_hist[base+2], h3=g_hist[base+3];
        float c0=h0.x,c1=h1.x,c2=h2.x,c3=h3.x;
        float t0=h0.y,t1=h1.y,t2=h2.y,t3=h3.y;
        float s0=h0.z,s1=h1.z,s2=h2.z,s3=h3.z;
        shC[tid]=c0+c1+c2+c3; shA[tid]=t0+t1+t2+t3; shB[tid]=s0+s1+s2+s3;
        __syncthreads();
        for (int off=1; off<NTHR; off<<=1){
            float vC=shC[tid], vT=shA[tid], vS=shB[tid];
            float uC=0.f,uT=0.f,uS=0.f;
            if (tid>=off){ uC=shC[tid-off]; uT=shA[tid-off]; uS=shB[tid-off]; }
            __syncthreads();
            shC[tid]=vC+uC; shA[tid]=vT+uT; shB[tid]=vS+uS;
            __syncthreads();
        }
        float exC = tid? shC[tid-1]:0.f;
        float exT = tid? shA[tid-1]:0.f;
        float exS = tid? shB[tid-1]:0.f;
        g_binPack[base]   = make_float4(exT+t0,          exS+s0,          exC,          c0);
        g_binPack[base+1] = make_float4(exT+t0+t1,       exS+s0+s1,       exC+c0,       c1);
        g_binPack[base+2] = make_float4(exT+t0+t1+t2,    exS+s0+s1+s2,    exC+c0+c1,    c2);
        g_binPack[base+3] = make_float4(exT+t0+t1+t2+t3, exS+s0+s1+s2+s3, exC+c0+c1+c2, c3);
        float aggC=shC[NTHR-1], aggT=shA[NTHR-1], aggS=shB[NTHR-1];
        __threadfence();
        __syncthreads();
        if (tid==0) stvol4(&g_aggL[bid], make_float4(aggT, aggS, aggC, 1.0f));

        // --- gather all 64 group aggregates (flag-in-payload) ---
        if (tid < NLB){
            float4 a;
            for(;;){ a = ldvol4(&g_aggL[tid]); if (a.w != 0.f) break; __nanosleep(32); }
            shC[tid]=a.z; shA[tid]=a.x; shB[tid]=a.y;
        }
        __threadfence();
        __syncthreads();
        for (int off=1; off<NLB; off<<=1){
            float vC=0.f,vT=0.f,vS=0.f,uC=0.f,uT=0.f,uS=0.f;
            if (tid < NLB){
                vC=shC[tid]; vT=shA[tid]; vS=shB[tid];
                if (tid>=off){ uC=shC[tid-off]; uT=shA[tid-off]; uS=shB[tid-off]; }
            }
            __syncthreads();
            if (tid < NLB){ shC[tid]=vC+uC; shA[tid]=vT+uT; shB[tid]=vS+uS; }
            __syncthreads();
        }
        if (tid < NLB){
            shOffC[tid] = tid? shC[tid-1] : 0.f;
            shOffT[tid] = tid? shA[tid-1] : 0.f;
            shOffS[tid] = tid? shB[tid-1] : 0.f;
        }
        if (tid==0){ shTotT = shA[NLB-1]; shTotS = shB[NLB-1]; }
        __syncthreads();

        // --- scatter this block's 500 elements into bin-sorted order ---
        for (int i=tid; i<NPB; i+=NTHR){
            int id = bid*NPB + i;
            float4 p = g_pack[id];
            int j = binOf(p.z);
            int g = j >> 10;
            float4 bp = g_binPack[j];
            int pos = (int)shOffC[g] + (int)bp.z + atomicAdd(&g_cur[j], 1);
            g_sorted[pos] = make_float4(p.z, p.x, p.y, 0.f);
        }
        teamBarL();

        // --- L1 reduction: P_t(a) = suffix of bins + exact boundary-bin scan ---
        float contrib = 0.f;
        float Ttot = shTotT, Stot = shTotS;
        for (int i=tid; i<NPB; i+=NTHR){
            int id = bid*NPB + i;
            float4 p = g_pack[id];              // t=x, s=y, d=z
            float x = -p.z;
            int j = binOf(x);
            int g = j >> 10;
            float4 bp = g_binPack[j];
            float pt = Ttot - (shOffT[g] + bp.x);
            float ps = Stot - (shOffS[g] + bp.y);
            int e0 = (int)shOffC[g] + (int)bp.z;
            int cnt = (int)bp.w;
            for (int m=e0; m<e0+cnt; ++m){
                float4 e = g_sorted[m];
                if (e.x > x){ pt += e.y; ps += e.z; }
            }
            contrib += p.x*(2.f*pt - Ttot) - p.y*(2.f*ps - Stot);
        }
        float r2 = blockSum(contrib, shR);
        if (tid==0) atomicAdd(&g_l1, (double)r2);

        // --- cleanup for next replay (all readers done: after teamBarL) ---
        float4 z4 = make_float4(0.f,0.f,0.f,0.f);
        g_hist[base]=z4; g_hist[base+1]=z4; g_hist[base+2]=z4; g_hist[base+3]=z4;
        for (int i=tid; i<GRPL; i+=NTHR) g_cur[bid*GRPL + i] = 0;
        if (tid==0) g_aggL[bid] = z4;
    } else {
        // =================== TEAM G: Gram sub losses, 4x4 tiles ===================
        const int NTG = KK*16*16;   // 1280 (BxB in 4x4 tiles)
        const int NTH = KK*25*25;   // 3125 (CxC in 4x4 tiles)
        int gid = (bid-NLB)*NTHR + tid;
        float val = 0.f;
        if (gid < NTG){
            int k  = gid >> 8;
            int r  = gid & 255;
            int i0 = (r >> 4) << 2;
            int j0 = (r & 15) << 2;
            const float* T = g_tk + k*BB*CC;
            const float* S = g_sk + k*BB*CC;
            float acc[16];
            #pragma unroll
            for (int q=0;q<16;q++) acc[q]=0.f;
            for (int c=0;c<CC;c++){
                float ti[4], tj[4], si[4], sj[4];
                #pragma unroll
                for (int d2=0;d2<4;d2++){
                    ti[d2]=T[(i0+d2)*CC+c]; tj[d2]=T[(j0+d2)*CC+c];
                    si[d2]=S[(i0+d2)*CC+c]; sj[d2]=S[(j0+d2)*CC+c];
                }
                #pragma unroll
                for (int di=0;di<4;di++)
                    #pragma unroll
                    for (int dj=0;dj<4;dj++)
                        acc[di*4+dj] += ti[di]*tj[dj] - si[di]*sj[dj];
            }
            #pragma unroll
            for (int q=0;q<16;q++) val += acc[q]*acc[q];
        } else if (gid < NTG + NTH){
            int u  = gid - NTG;
            int k  = u / 625;
            int r  = u - k*625;
            int i0 = (r / 25) * 4;
            int j0 = (r % 25) * 4;
            const float* T = g_tk + k*BB*CC;
            const float* S = g_sk + k*BB*CC;
            float acc[16];
            #pragma unroll
            for (int q=0;q<16;q++) acc[q]=0.f;
            for (int b2=0;b2<BB;b2++){
                float4 t4i = *(const float4*)(T + b2*CC + i0);
                float4 t4j = *(const float4*)(T + b2*CC + j0);
                float4 s4i = *(const float4*)(S + b2*CC + i0);
                float4 s4j = *(const float4*)(S + b2*CC + j0);
                float ti[4]={t4i.x,t4i.y,t4i.z,t4i.w};
                float tj[4]={t4j.x,t4j.y,t4j.z,t4j.w};
                float si[4]={s4i.x,s4i.y,s4i.z,s4i.w};
                float sj[4]={s4j.x,s4j.y,s4j.z,s4j.w};
                #pragma unroll
                for (int di=0;di<4;di++)
                    #pragma unroll
                    for (int dj=0;dj<4;dj++)
                        acc[di*4+dj] += ti[di]*tj[dj] - si[di]*sj[dj];
            }
            #pragma unroll
            for (int q=0;q<16;q++) val += acc[q]*acc[q];
        }
        float r2 = blockSum(val, shR);
        if (tid==0) atomicAdd(&g_sub, (double)r2);
    }

    // ============ Last block out does the final combine (no grid barrier) ============
    __threadfence();
    __syncthreads();
    if (tid == 0){
        if (atomicAdd(&g_done, 1u) == NBLK-1u){
            __threadfence();
            double ce = g_ce / (double)BB;
            double kd = 0.0;
            #pragma unroll
            for (int k=0;k<KK;k++){
                double T = (double)(k+1);
                kd += (g_kl[k] / (double)(BB*CC)) * (0.7*T*T) + ce * 0.3;
            }
            double tt=g_tt, ss2=g_ss, ts2=g_ts;
            double l2 = 0.00025*(tt*tt - 2.0*ts2*ts2 + ss2*ss2);
            out[0] = (float)(kd + 0.00025*g_l1 + l2 + g_sub);
            // reset state for next graph replay
            g_tt = 0.0; g_ss = 0.0; g_ts = 0.0;
            g_ce = 0.0; g_l1 = 0.0; g_sub = 0.0;
            #pragma unroll
            for (int k=0;k<KK;k++) g_kl[k] = 0.0;
            float4 z4 = make_float4(0.f,0.f,0.f,0.f);
            for (int i=0;i<NAB;i++) g_aflag[i] = z4;
            g_done = 0u;
        }
    }
}

// ---------------- launch ----------------
extern "C" void kernel_launch(void* const* d_in, const int* in_sizes, int n_in,
                              void* d_out, int out_size){
    (void)in_sizes; (void)n_in; (void)out_size;
    const float* ls  = (const float*)d_in[0];  // logits_student [64,100]
    const float* lt  = (const float*)d_in[1];  // logits_teacher [64,100]
    const int*   tgt = (const int*)  d_in[2];  // target [64]
    float* out = (float*)d_out;

    fused_kernel<<<NBLK, NTHR>>>(ls, lt, tgt, out);
}